// round 16
// baseline (speedup 1.0000x reference)
#include <cuda_runtime.h>
#include <cuda_fp16.h>
#include <math.h>

#define NN 100000
#define NE 3200000
#define HID 16
#define ES  (NE / 4)             // 800000 edge stripe
#define GG  ((NN + 63) / 64)     // gemm tiles (1563, 64 nodes each)
#define GE  (NE / 1024)          // deg blocks, 4 edges/thread (3125)
#define GT  (GG + GE)            // 4688 fused blocks
#define XPITCH 132               // padded x row pitch (words)

// Scratch (static device globals — zero-initialized at load)
__device__ float  d_deg [NN];    // zero at load; re-zeroed by k_dinv_scale
__device__ float  d_dinv[NN];
__device__ __half d_u  [NN * HID];   // unscaled x@W1, fp16
__device__ __half d_gh [NN * HID];   // dinv-scaled features, fp16 (32B/node)
__device__ float  d_agg[NN * HID];   // fp32 accumulation

// ---- fused: interleaved gemm tiles (every 3rd block) + deg atomic blocks ----
// deg phase: 4 edges/thread, int4/float4 loads, fire-and-forget REDs.
#define WPAD 132
__global__ void k_gemm1_deg(const float* __restrict__ x,
                            const float* __restrict__ W1,
                            const int* __restrict__ col,
                            const float* __restrict__ ew) {
    int B = blockIdx.x;
    if (B % 3 != 0) {
        int db = B - B / 3 - 1;            // 0..GE-1
        int qi = db * 256 + threadIdx.x;   // quad index < NE/4
        int4   c4 = __ldg((const int4*)col + qi);
        float4 w4 = __ldg((const float4*)ew + qi);
        atomicAdd(&d_deg[c4.x], w4.x);     // RED (result unused)
        atomicAdd(&d_deg[c4.y], w4.y);
        atomicAdd(&d_deg[c4.z], w4.z);
        atomicAdd(&d_deg[c4.w], w4.w);
        return;
    }
    int gb = B / 3;                        // 0..GG-1
    __shared__ float xs[64 * XPITCH];
    __shared__ float Wt[HID * WPAD];
    int t = threadIdx.x;
    int base = gb * 64;
    int nvalid = NN - base; if (nvalid > 64) nvalid = 64;

    const float4* xg = (const float4*)x + (size_t)base * 32;
    for (int j = t; j < nvalid * 32; j += 256) {
        int n = j >> 5, k4 = j & 31;
        *(float4*)(xs + n * XPITCH + k4 * 4) = xg[j];
    }
    for (int j = t; j < 128 * HID; j += 256) {
        int k = j >> 4, c = j & 15;
        Wt[c * WPAD + k] = W1[j];
    }
    __syncthreads();

    int c  = t & 15;
    int n0 = (t >> 4) * 4;

    float acc0 = 0.f, acc1 = 0.f, acc2 = 0.f, acc3 = 0.f;
    const float* wrow = Wt + c * WPAD;
    const float* x0 = xs + (n0 + 0) * XPITCH;
    const float* x1 = xs + (n0 + 1) * XPITCH;
    const float* x2 = xs + (n0 + 2) * XPITCH;
    const float* x3 = xs + (n0 + 3) * XPITCH;
#pragma unroll
    for (int kk = 0; kk < 32; kk++) {
        float4 wv = *(const float4*)(wrow + kk * 4);
        float4 a  = *(const float4*)(x0 + kk * 4);
        float4 b  = *(const float4*)(x1 + kk * 4);
        float4 d  = *(const float4*)(x2 + kk * 4);
        float4 e  = *(const float4*)(x3 + kk * 4);
        acc0 += a.x*wv.x + a.y*wv.y + a.z*wv.z + a.w*wv.w;
        acc1 += b.x*wv.x + b.y*wv.y + b.z*wv.z + b.w*wv.w;
        acc2 += d.x*wv.x + d.y*wv.y + d.z*wv.z + d.w*wv.w;
        acc3 += e.x*wv.x + e.y*wv.y + e.z*wv.z + e.w*wv.w;
    }
    float accs[4] = {acc0, acc1, acc2, acc3};
#pragma unroll
    for (int m = 0; m < 4; m++) {
        int node = base + n0 + m;
        if (node < NN) {
            int idx = node * HID + c;
            d_u[idx]   = __float2half(accs[m]);
            d_agg[idx] = 0.0f;             // zero for edge pass 1
        }
    }
}

// ---- dinv = rsqrt(1+deg); gh = half(dinv*u); reset deg ----------------------
__global__ void k_dinv_scale() {
    int i = blockIdx.x * blockDim.x + threadIdx.x;   // half-row id
    cudaGridDependencySynchronize();                 // PDL
    if (i >= NN * 2) return;
    int node = i >> 1;
    float dv = rsqrtf(1.0f + d_deg[node]);
    uint4 uv = *((const uint4*)d_u + i);
    float2 f0 = __half22float2(*(const __half2*)&uv.x);
    float2 f1 = __half22float2(*(const __half2*)&uv.y);
    float2 f2 = __half22float2(*(const __half2*)&uv.z);
    float2 f3 = __half22float2(*(const __half2*)&uv.w);
    uint4 gv;
    *(__half2*)&gv.x = __floats2half2_rn(f0.x * dv, f0.y * dv);
    *(__half2*)&gv.y = __floats2half2_rn(f1.x * dv, f1.y * dv);
    *(__half2*)&gv.z = __floats2half2_rn(f2.x * dv, f2.y * dv);
    *(__half2*)&gv.w = __floats2half2_rn(f3.x * dv, f3.y * dv);
    *((uint4*)d_gh + i) = gv;
    if ((i & 1) == 0) {
        d_dinv[node] = dv;
        d_deg[node]  = 0.0f;
    }
}

// ---- edge scatter: agg[col] += ew * gh[row] ---------------------------------
// 2 lanes/edge (uint4 gather = 8 halves/lane, 2 REDs/lane), 4 striped
// edges/thread: index-load instructions halved vs 4-lane scheme.
__global__ void k_edges(const int* __restrict__ row,
                        const int* __restrict__ col,
                        const float* __restrict__ ew) {
    int idx = blockIdx.x * 256 + threadIdx.x;
    int e0 = idx >> 1;          // edge slot 0..ES-1
    int hh = idx & 1;           // half: channels 0-7 or 8-15

    int   r[4], d[4];
    float w[4];
    if (e0 < ES) {
#pragma unroll
        for (int j = 0; j < 4; j++) {
            int e = e0 + j * ES;
            r[j] = __ldg(row + e);
            d[j] = __ldg(col + e);
            w[j] = __ldg(ew  + e);
        }
    }
    cudaGridDependencySynchronize();       // PDL: gh/agg now valid
    if (e0 >= ES) return;

    uint4 gv[4];
#pragma unroll
    for (int j = 0; j < 4; j++)
        gv[j] = __ldg((const uint4*)d_gh + r[j] * 2 + hh);   // 8 halves
#pragma unroll
    for (int j = 0; j < 4; j++) {
        float2 f0 = __half22float2(*(const __half2*)&gv[j].x);
        float2 f1 = __half22float2(*(const __half2*)&gv[j].y);
        float2 f2 = __half22float2(*(const __half2*)&gv[j].z);
        float2 f3 = __half22float2(*(const __half2*)&gv[j].w);
        float* p = d_agg + d[j] * HID + hh * 8;
        asm volatile("red.global.add.v4.f32 [%0], {%1,%2,%3,%4};"
                     :: "l"(p), "f"(w[j] * f0.x), "f"(w[j] * f0.y),
                        "f"(w[j] * f1.x), "f"(w[j] * f1.y)
                     : "memory");
        asm volatile("red.global.add.v4.f32 [%0], {%1,%2,%3,%4};"
                     :: "l"(p + 4), "f"(w[j] * f2.x), "f"(w[j] * f2.y),
                        "f"(w[j] * f3.x), "f"(w[j] * f3.y)
                     : "memory");
    }
}

// ---- fused: h = relu(dinv*(agg+g)+b1);  gh = half(dinv*(h @ W2)); zero agg --
#define HPITCH 20
#define W2PITCH 36
__global__ void k_combine_gemm2(const float* __restrict__ b1,
                                const float* __restrict__ W2) {
    __shared__ float hs[64 * HPITCH];
    __shared__ float W2t[HID * W2PITCH];
    int t = threadIdx.x;
    if (t < HID * HID) {                   // PDL prologue (external input)
        int k = t >> 4, c = t & 15;
        W2t[c * W2PITCH + k] = W2[t];
    }
    float bc = __ldg(b1 + (t & 15));
    cudaGridDependencySynchronize();       // PDL: agg (pass 1) now valid

    int base = blockIdx.x * 64;
    int c    = t & 15;
    int n0   = (t >> 4) * 4;

    float dvv[4];
#pragma unroll
    for (int m = 0; m < 4; m++) {
        int node = base + n0 + m;
        if (node < NN) {
            int idx  = node * HID + c;
            float dv = d_dinv[node];
            dvv[m] = dv;
            float g  = __half2float(d_gh[idx]);
            hs[(n0 + m) * HPITCH + c] =
                fmaxf(dv * (d_agg[idx] + g) + bc, 0.0f);
        } else dvv[m] = 0.0f;
    }
    __syncthreads();

    const float* wrow = W2t + c * W2PITCH;
    float4 wv[4];
#pragma unroll
    for (int q = 0; q < 4; q++) wv[q] = *(const float4*)(wrow + q * 4);

#pragma unroll
    for (int m = 0; m < 4; m++) {
        int node = base + n0 + m;
        if (node >= NN) break;
        const float* hrow = hs + (n0 + m) * HPITCH;
        float acc = 0.0f;
#pragma unroll
        for (int q = 0; q < 4; q++) {
            float4 hv = *(const float4*)(hrow + q * 4);
            acc += hv.x*wv[q].x + hv.y*wv[q].y + hv.z*wv[q].z + hv.w*wv[q].w;
        }
        int idx = node * HID + c;
        d_gh[idx]  = __float2half(dvv[m] * acc);
        d_agg[idx] = 0.0f;                 // zero for edge pass 2
    }
}

// ---- final: out = relu(dinv*(agg+g)+b2) @ Wout + bout -----------------------
__global__ void k_out(const float* __restrict__ b2,
                      const float* __restrict__ Wout,
                      const float* __restrict__ bout,
                      float* __restrict__ out) {
    int i = blockIdx.x * blockDim.x + threadIdx.x;
    float w[HID], bb[HID];
#pragma unroll
    for (int c = 0; c < HID; c++) { w[c] = __ldg(Wout + c); bb[c] = __ldg(b2 + c); }
    float bo = __ldg(bout);
    cudaGridDependencySynchronize();       // PDL: agg (pass 2) now valid
    if (i >= NN) return;

    float dv = d_dinv[i];
    const float4* a4 = (const float4*)d_agg + i * 4;
    const uint2*  g4 = (const uint2*)d_gh + i * 4;
    float s = 0.0f;
#pragma unroll
    for (int q = 0; q < 4; q++) {
        float4 a = a4[q];
        uint2 gb = g4[q];
        float2 g01 = __half22float2(*(const __half2*)&gb.x);
        float2 g23 = __half22float2(*(const __half2*)&gb.y);
        int c = q * 4;
        s += fmaxf(dv * (a.x + g01.x) + bb[c + 0], 0.0f) * w[c + 0];
        s += fmaxf(dv * (a.y + g01.y) + bb[c + 1], 0.0f) * w[c + 1];
        s += fmaxf(dv * (a.z + g23.x) + bb[c + 2], 0.0f) * w[c + 2];
        s += fmaxf(dv * (a.w + g23.y) + bb[c + 3], 0.0f) * w[c + 3];
    }
    out[i] = s + bo;
}

// ---- PDL launch helper -------------------------------------------------------
template <typename F, typename... Args>
static void launch_pdl(F f, int grid, int block, Args... args) {
    cudaLaunchConfig_t cfg = {};
    cfg.gridDim  = dim3(grid, 1, 1);
    cfg.blockDim = dim3(block, 1, 1);
    cfg.dynamicSmemBytes = 0;
    cfg.stream = 0;
    cudaLaunchAttribute attr[1];
    attr[0].id = cudaLaunchAttributeProgrammaticStreamSerialization;
    attr[0].val.programmaticStreamSerializationAllowed = 1;
    cfg.attrs = attr;
    cfg.numAttrs = 1;
    cudaLaunchKernelEx(&cfg, f, args...);
}

extern "C" void kernel_launch(void* const* d_in, const int* in_sizes, int n_in,
                              void* d_out, int out_size) {
    const float* x    = (const float*)d_in[0];
    const int*   ei   = (const int*)d_in[1];   // [2, NE] int32
    const float* ea   = (const float*)d_in[2];
    const float* W1   = (const float*)d_in[5];
    const float* b1   = (const float*)d_in[6];
    const float* W2   = (const float*)d_in[7];
    const float* b2   = (const float*)d_in[8];
    const float* Wout = (const float*)d_in[9];
    const float* bout = (const float*)d_in[10];
    float*       out  = (float*)d_out;

    const int* row = ei;
    const int* col = ei + NE;

    const int T = 256;
    int gN  = (NN + T - 1) / T;
    int gHR = (NN * 2 + T - 1) / T;
    int gE2 = (ES * 2 + T - 1) / T;        // 2 lanes/edge-slot

    k_gemm1_deg<<<GT, T>>>(x, W1, col, ea);
    launch_pdl(k_dinv_scale, gHR, T);
    launch_pdl(k_edges, gE2, T, row, col, ea);
    launch_pdl(k_combine_gemm2, GG, T, b1, W2);
    launch_pdl(k_edges, gE2, T, row, col, ea);
    launch_pdl(k_out, gN, T, b2, Wout, bout, out);
}

// round 17
// speedup vs baseline: 1.1406x; 1.1406x over previous
#include <cuda_runtime.h>
#include <cuda_fp16.h>
#include <math.h>

#define NN 100000
#define NE 3200000
#define HID 16
#define ES  (NE / 4)             // 800000 edge stripe
#define GG  ((NN + 63) / 64)     // gemm tiles (1563, 64 nodes each)
#define GE  (NE / 1024)          // deg blocks, 4 edges/thread (3125)
#define GT  (GG + GE)            // 4688 fused blocks
#define XPITCH 132               // padded x row pitch (words)

// Scratch (static device globals — zero-initialized at load)
__device__ float  d_deg [NN];    // zero at load; re-zeroed by k_dinv_scale
__device__ float  d_dinv[NN];
__device__ __half d_u  [NN * HID];   // unscaled x@W1, fp16
__device__ __half d_gh [NN * HID];   // dinv-scaled features, fp16 (32B/node)
__device__ float  d_agg[NN * HID];   // fp32 accumulation

// ---- fused: interleaved gemm tiles (every 3rd block) + deg atomic blocks ----
// deg phase: 4 edges/thread, int4/float4 loads, fire-and-forget REDs.
#define WPAD 132
__global__ void k_gemm1_deg(const float* __restrict__ x,
                            const float* __restrict__ W1,
                            const int* __restrict__ col,
                            const float* __restrict__ ew) {
    int B = blockIdx.x;
    if (B % 3 != 0) {
        int db = B - B / 3 - 1;            // 0..GE-1
        int qi = db * 256 + threadIdx.x;   // quad index < NE/4
        int4   c4 = __ldg((const int4*)col + qi);
        float4 w4 = __ldg((const float4*)ew + qi);
        atomicAdd(&d_deg[c4.x], w4.x);     // RED (result unused)
        atomicAdd(&d_deg[c4.y], w4.y);
        atomicAdd(&d_deg[c4.z], w4.z);
        atomicAdd(&d_deg[c4.w], w4.w);
        return;
    }
    int gb = B / 3;                        // 0..GG-1
    __shared__ float xs[64 * XPITCH];
    __shared__ float Wt[HID * WPAD];
    int t = threadIdx.x;
    int base = gb * 64;
    int nvalid = NN - base; if (nvalid > 64) nvalid = 64;

    const float4* xg = (const float4*)x + (size_t)base * 32;
    for (int j = t; j < nvalid * 32; j += 256) {
        int n = j >> 5, k4 = j & 31;
        *(float4*)(xs + n * XPITCH + k4 * 4) = xg[j];
    }
    for (int j = t; j < 128 * HID; j += 256) {
        int k = j >> 4, c = j & 15;
        Wt[c * WPAD + k] = W1[j];
    }
    __syncthreads();

    int c  = t & 15;
    int n0 = (t >> 4) * 4;

    float acc0 = 0.f, acc1 = 0.f, acc2 = 0.f, acc3 = 0.f;
    const float* wrow = Wt + c * WPAD;
    const float* x0 = xs + (n0 + 0) * XPITCH;
    const float* x1 = xs + (n0 + 1) * XPITCH;
    const float* x2 = xs + (n0 + 2) * XPITCH;
    const float* x3 = xs + (n0 + 3) * XPITCH;
#pragma unroll
    for (int kk = 0; kk < 32; kk++) {
        float4 wv = *(const float4*)(wrow + kk * 4);
        float4 a  = *(const float4*)(x0 + kk * 4);
        float4 b  = *(const float4*)(x1 + kk * 4);
        float4 d  = *(const float4*)(x2 + kk * 4);
        float4 e  = *(const float4*)(x3 + kk * 4);
        acc0 += a.x*wv.x + a.y*wv.y + a.z*wv.z + a.w*wv.w;
        acc1 += b.x*wv.x + b.y*wv.y + b.z*wv.z + b.w*wv.w;
        acc2 += d.x*wv.x + d.y*wv.y + d.z*wv.z + d.w*wv.w;
        acc3 += e.x*wv.x + e.y*wv.y + e.z*wv.z + e.w*wv.w;
    }
    float accs[4] = {acc0, acc1, acc2, acc3};
#pragma unroll
    for (int m = 0; m < 4; m++) {
        int node = base + n0 + m;
        if (node < NN) {
            int idx = node * HID + c;
            d_u[idx]   = __float2half(accs[m]);
            d_agg[idx] = 0.0f;             // zero for edge pass 1
        }
    }
}

// ---- dinv = rsqrt(1+deg); gh = half(dinv*u); reset deg ----------------------
__global__ void k_dinv_scale() {
    int i = blockIdx.x * blockDim.x + threadIdx.x;   // half-row id
    cudaGridDependencySynchronize();                 // PDL
    if (i >= NN * 2) return;
    int node = i >> 1;
    float dv = rsqrtf(1.0f + d_deg[node]);
    uint4 uv = *((const uint4*)d_u + i);
    float2 f0 = __half22float2(*(const __half2*)&uv.x);
    float2 f1 = __half22float2(*(const __half2*)&uv.y);
    float2 f2 = __half22float2(*(const __half2*)&uv.z);
    float2 f3 = __half22float2(*(const __half2*)&uv.w);
    uint4 gv;
    *(__half2*)&gv.x = __floats2half2_rn(f0.x * dv, f0.y * dv);
    *(__half2*)&gv.y = __floats2half2_rn(f1.x * dv, f1.y * dv);
    *(__half2*)&gv.z = __floats2half2_rn(f2.x * dv, f2.y * dv);
    *(__half2*)&gv.w = __floats2half2_rn(f3.x * dv, f3.y * dv);
    *((uint4*)d_gh + i) = gv;
    if ((i & 1) == 0) {
        d_dinv[node] = dv;
        d_deg[node]  = 0.0f;
    }
}

// ---- edge scatter: agg[col] += ew * gh[row] (R15 4-lane scheme, proven) -----
__global__ void k_edges(const int* __restrict__ row,
                        const int* __restrict__ col,
                        const float* __restrict__ ew) {
    int idx = blockIdx.x * 256 + threadIdx.x;
    int e0 = idx >> 2;
    int q  = idx & 3;

    int   r[4], d[4];
    float w[4];
    if (e0 < ES) {
#pragma unroll
        for (int j = 0; j < 4; j++) {
            int e = e0 + j * ES;
            r[j] = __ldg(row + e);
            d[j] = __ldg(col + e);
            w[j] = __ldg(ew  + e);
        }
    }
    cudaGridDependencySynchronize();       // PDL: gh/agg now valid
    if (e0 >= ES) return;

    uint2 gv[4];
#pragma unroll
    for (int j = 0; j < 4; j++)
        gv[j] = __ldg((const uint2*)d_gh + r[j] * 4 + q);
#pragma unroll
    for (int j = 0; j < 4; j++) {
        float2 f01 = __half22float2(*(const __half2*)&gv[j].x);
        float2 f23 = __half22float2(*(const __half2*)&gv[j].y);
        float* p = d_agg + d[j] * HID + q * 4;
        asm volatile("red.global.add.v4.f32 [%0], {%1,%2,%3,%4};"
                     :: "l"(p), "f"(w[j] * f01.x), "f"(w[j] * f01.y),
                        "f"(w[j] * f23.x), "f"(w[j] * f23.y)
                     : "memory");
    }
}

// ---- fused: h = relu(dinv*(agg+g)+b1);  gh = half(dinv*(h @ W2)); zero agg --
#define HPITCH 20
#define W2PITCH 36
__global__ void k_combine_gemm2(const float* __restrict__ b1,
                                const float* __restrict__ W2) {
    __shared__ float hs[64 * HPITCH];
    __shared__ float W2t[HID * W2PITCH];
    int t = threadIdx.x;
    if (t < HID * HID) {                   // PDL prologue (external input)
        int k = t >> 4, c = t & 15;
        W2t[c * W2PITCH + k] = W2[t];
    }
    float bc = __ldg(b1 + (t & 15));
    cudaGridDependencySynchronize();       // PDL: agg (pass 1) now valid

    int base = blockIdx.x * 64;
    int c    = t & 15;
    int n0   = (t >> 4) * 4;

    float dvv[4];
#pragma unroll
    for (int m = 0; m < 4; m++) {
        int node = base + n0 + m;
        if (node < NN) {
            int idx  = node * HID + c;
            float dv = d_dinv[node];
            dvv[m] = dv;
            float g  = __half2float(d_gh[idx]);
            hs[(n0 + m) * HPITCH + c] =
                fmaxf(dv * (d_agg[idx] + g) + bc, 0.0f);
        } else dvv[m] = 0.0f;
    }
    __syncthreads();

    const float* wrow = W2t + c * W2PITCH;
    float4 wv[4];
#pragma unroll
    for (int q = 0; q < 4; q++) wv[q] = *(const float4*)(wrow + q * 4);

#pragma unroll
    for (int m = 0; m < 4; m++) {
        int node = base + n0 + m;
        if (node >= NN) break;
        const float* hrow = hs + (n0 + m) * HPITCH;
        float acc = 0.0f;
#pragma unroll
        for (int q = 0; q < 4; q++) {
            float4 hv = *(const float4*)(hrow + q * 4);
            acc += hv.x*wv[q].x + hv.y*wv[q].y + hv.z*wv[q].z + hv.w*wv[q].w;
        }
        int idx = node * HID + c;
        d_gh[idx]  = __float2half(dvv[m] * acc);
        d_agg[idx] = 0.0f;                 // zero for edge pass 2
    }
}

// ---- final: out = relu(dinv*(agg+g)+b2) @ Wout + bout -----------------------
__global__ void k_out(const float* __restrict__ b2,
                      const float* __restrict__ Wout,
                      const float* __restrict__ bout,
                      float* __restrict__ out) {
    int i = blockIdx.x * blockDim.x + threadIdx.x;
    float w[HID], bb[HID];
#pragma unroll
    for (int c = 0; c < HID; c++) { w[c] = __ldg(Wout + c); bb[c] = __ldg(b2 + c); }
    float bo = __ldg(bout);
    cudaGridDependencySynchronize();       // PDL: agg (pass 2) now valid
    if (i >= NN) return;

    float dv = d_dinv[i];
    const float4* a4 = (const float4*)d_agg + i * 4;
    const uint2*  g4 = (const uint2*)d_gh + i * 4;
    float s = 0.0f;
#pragma unroll
    for (int q = 0; q < 4; q++) {
        float4 a = a4[q];
        uint2 gb = g4[q];
        float2 g01 = __half22float2(*(const __half2*)&gb.x);
        float2 g23 = __half22float2(*(const __half2*)&gb.y);
        int c = q * 4;
        s += fmaxf(dv * (a.x + g01.x) + bb[c + 0], 0.0f) * w[c + 0];
        s += fmaxf(dv * (a.y + g01.y) + bb[c + 1], 0.0f) * w[c + 1];
        s += fmaxf(dv * (a.z + g23.x) + bb[c + 2], 0.0f) * w[c + 2];
        s += fmaxf(dv * (a.w + g23.y) + bb[c + 3], 0.0f) * w[c + 3];
    }
    out[i] = s + bo;
}

// ---- PDL launch helper -------------------------------------------------------
template <typename F, typename... Args>
static void launch_pdl(F f, int grid, int block, Args... args) {
    cudaLaunchConfig_t cfg = {};
    cfg.gridDim  = dim3(grid, 1, 1);
    cfg.blockDim = dim3(block, 1, 1);
    cfg.dynamicSmemBytes = 0;
    cfg.stream = 0;
    cudaLaunchAttribute attr[1];
    attr[0].id = cudaLaunchAttributeProgrammaticStreamSerialization;
    attr[0].val.programmaticStreamSerializationAllowed = 1;
    cfg.attrs = attr;
    cfg.numAttrs = 1;
    cudaLaunchKernelEx(&cfg, f, args...);
}

extern "C" void kernel_launch(void* const* d_in, const int* in_sizes, int n_in,
                              void* d_out, int out_size) {
    const float* x    = (const float*)d_in[0];
    const int*   ei   = (const int*)d_in[1];   // [2, NE] int32
    const float* ea   = (const float*)d_in[2];
    const float* W1   = (const float*)d_in[5];
    const float* b1   = (const float*)d_in[6];
    const float* W2   = (const float*)d_in[7];
    const float* b2   = (const float*)d_in[8];
    const float* Wout = (const float*)d_in[9];
    const float* bout = (const float*)d_in[10];
    float*       out  = (float*)d_out;

    const int* row = ei;
    const int* col = ei + NE;

    const int T = 256;
    int gN  = (NN + T - 1) / T;
    int gHR = (NN * 2 + T - 1) / T;
    int gE4 = (ES * 4 + T - 1) / T;        // R15 4-lane edge scheme

    k_gemm1_deg<<<GT, T>>>(x, W1, col, ea);
    launch_pdl(k_dinv_scale, gHR, T);
    launch_pdl(k_edges, gE4, T, row, col, ea);
    launch_pdl(k_combine_gemm2, GG, T, b1, W2);
    launch_pdl(k_edges, gE4, T, row, col, ea);
    launch_pdl(k_out, gN, T, b2, Wout, bout, out);
}